// round 14
// baseline (speedup 1.0000x reference)
#include <cuda_runtime.h>

// SelfAttention_61804579389661 — GB300 sm_103a — Round 14
//
// Algebraic simplification: softmax over a size-1 axis is identically 1.0,
// so attention == 1 and context[b,u] = sum_s hidden_states[b,s,u]. Pure
// 256 MiB read-reduce, bandwidth-bound.
//
// R14: last untested cell in the strided-family grid — warp-contiguous
// 512B segments. Identical to the converged winner (512 thr/block, zero
// cross-block communication, #pragma unroll 16, ones in epilogue) except
// C4=32 lanes per chunk: each warp reads ONE contiguous 512B segment per
// step instead of two 256B segments 4KB apart. Grid 32x8=256 blocks,
// SPHASE=16, 128 iterations. (Occupancy halves; R3-vs-R4 showed occupancy
// is neutral in this family.)
//
// Output layout (out_size = 98304 fp32):
//   [0      .. 32767 ]  context   (B=32, U=1024)
//   [32768  .. 98303 ]  attention (B=32, S=2048, 1) == 1.0f

#define BB 32
#define SS 2048
#define UU 1024
#define U4 (UU / 4)        // 256 float4 per row
#define NCHUNK 8           // U-chunks per batch row
#define C4 (U4 / NCHUNK)   // 32 float4 lanes per chunk (= 512B per warp)
#define NT 512             // threads per block
#define SPHASE (NT / C4)   // 16 s-strides per block

__global__ void __launch_bounds__(NT) fused_kernel(const float4* __restrict__ hs,
                                                   float* __restrict__ out) {
    const int b = blockIdx.x;   // 0..31
    const int y = blockIdx.y;   // 0..7
    const int t = threadIdx.x;  // 0..511

    // ---- block (b, y): sum hs[b, :, y*128 : y*128+128] over all S ----
    const int lane = t & (C4 - 1);      // 0..31 -> float4 column in chunk
    const int srow = t >> 5;            // 0..15 -> starting s, stride 16

    const float4* __restrict__ base =
        hs + ((size_t)b * SS + srow) * U4 + y * C4 + lane;

    float4 acc = make_float4(0.f, 0.f, 0.f, 0.f);
#pragma unroll 16
    for (int s = 0; s < SS / SPHASE; ++s) {             // 128 iters, stride 16 rows
        float4 v = base[(size_t)s * SPHASE * U4];
        acc.x += v.x; acc.y += v.y; acc.z += v.z; acc.w += v.w;
    }

    // ---- deterministic in-block reduction of the 16 s-phases ----
    __shared__ float4 smem[NT];
    smem[t] = acc;
    __syncthreads();

    if (t < C4) {
        float4 r = make_float4(0.f, 0.f, 0.f, 0.f);
#pragma unroll
        for (int k = 0; k < SPHASE; ++k) {              // fixed order
            float4 v = smem[k * C4 + t];
            r.x += v.x; r.y += v.y; r.z += v.z; r.w += v.w;
        }
        ((float4*)out)[b * U4 + y * C4 + t] = r;
    }

    // ---- epilogue: attention region = 1.0, spread over all 256 blocks ----
    // 16384 float4 total / 256 blocks = 64 float4 per block (threads 64..127,
    // disjoint from the context-writing threads 0..31).
    if (t >= 64 && t < 128) {
        float4* ones = (float4*)(out + BB * UU);
        ones[(b * NCHUNK + y) * 64 + (t - 64)] = make_float4(1.f, 1.f, 1.f, 1.f);
    }
}

extern "C" void kernel_launch(void* const* d_in, const int* in_sizes, int n_in,
                              void* d_out, int out_size) {
    // Inputs: [0]=s_prev, [1]=hidden_states, [2]=Ww, [3]=Wb, [4]=Uw, [5]=Ub,
    //         [6]=Vw, [7]=Vb. Only hidden_states is live.
    const float4* hs = (const float4*)d_in[1];
    float* out = (float*)d_out;

    dim3 grid(BB, NCHUNK);
    fused_kernel<<<grid, NT>>>(hs, out);
}

// round 15
// speedup vs baseline: 1.0051x; 1.0051x over previous
#include <cuda_runtime.h>

// SelfAttention_61804579389661 — GB300 sm_103a — FINAL
// (best measured across 3 runs of this exact source: kernel 42.62-43.10us,
//  HBM 6341-6390 GB/s = ~99% of the empirical streaming cap; bench
//  43.49-43.74us, rel_err 2.05e-7)
//
// Algebraic simplification: softmax over a size-1 axis is identically 1.0,
// so attention == 1 and context[b,u] = sum_s hidden_states[b,s,u]. The
// entire tanh/GEMM pipeline in the reference is dead code; the problem is a
// pure 256 MiB read-reduce, bandwidth-bound (floor ~42.2us at 6.35 TB/s).
//
// Fully-explored design grid (R1-R14), evidence per axis:
//  - decomposition: strided U-chunk (6.33-6.39 TB/s) > contiguous-per-block
//    (5.98-6.0 TB/s), at both high and low occupancy;
//  - fusion: zero cross-block communication > last-block reduce (+2us tail)
//    > separate finalize launch (+5us);
//  - occupancy 43% vs 85%: neutral (R14 vs R13); keep 512 thr, 512 blocks;
//  - warp segment width 256B vs 512B: neutral (R14);
//  - load scheduling: simple dependent-index loop + #pragma unroll 16
//    (ptxas-scheduled) is the optimum: unroll 8 = 6314, 16 = 6341-6390;
//    manual register batching (R5) and two-chain unroll-32 (R11: regs 36,
//    occ 71%, 5525 GB/s) both regress;
//  - __ldcs: neutral; TMA: same path-independent LTS cap, no headroom;
//  - all-ones attention written in the epilogue of the same launch.
//
// Output layout (out_size = 98304 fp32):
//   [0      .. 32767 ]  context   (B=32, U=1024)
//   [32768  .. 98303 ]  attention (B=32, S=2048, 1) == 1.0f

#define BB 32
#define SS 2048
#define UU 1024
#define U4 (UU / 4)        // 256 float4 per row
#define NCHUNK 16          // U-chunks per batch row
#define C4 (U4 / NCHUNK)   // 16 float4 lanes per chunk
#define NT 512             // threads per block
#define SPHASE (NT / C4)   // 32 s-strides per block

__global__ void __launch_bounds__(NT) fused_kernel(const float4* __restrict__ hs,
                                                   float* __restrict__ out) {
    const int b = blockIdx.x;   // 0..31
    const int y = blockIdx.y;   // 0..15
    const int t = threadIdx.x;  // 0..511

    // ---- block (b, y): sum hs[b, :, y*64 : y*64+64] over all S ----
    const int lane = t & (C4 - 1);      // 0..15 -> float4 column in chunk
    const int srow = t >> 4;            // 0..31 -> starting s, stride 32

    const float4* __restrict__ base =
        hs + ((size_t)b * SS + srow) * U4 + y * C4 + lane;

    float4 acc = make_float4(0.f, 0.f, 0.f, 0.f);
#pragma unroll 16
    for (int s = 0; s < SS / SPHASE; ++s) {             // 64 iters, stride 32 rows
        float4 v = base[(size_t)s * SPHASE * U4];
        acc.x += v.x; acc.y += v.y; acc.z += v.z; acc.w += v.w;
    }

    // ---- deterministic in-block reduction of the 32 s-phases ----
    __shared__ float4 smem[NT];
    smem[t] = acc;
    __syncthreads();

    if (t < C4) {
        float4 r = make_float4(0.f, 0.f, 0.f, 0.f);
#pragma unroll
        for (int k = 0; k < SPHASE; ++k) {              // fixed order
            float4 v = smem[k * C4 + t];
            r.x += v.x; r.y += v.y; r.z += v.z; r.w += v.w;
        }
        ((float4*)out)[b * U4 + y * C4 + t] = r;
    }

    // ---- epilogue: attention region = 1.0, spread over all 512 blocks ----
    // 16384 float4 total / 512 blocks = 32 float4 per block (threads 32..63,
    // disjoint from the context-writing threads 0..15).
    if (t >= 32 && t < 64) {
        float4* ones = (float4*)(out + BB * UU);
        ones[(b * NCHUNK + y) * 32 + (t - 32)] = make_float4(1.f, 1.f, 1.f, 1.f);
    }
}

extern "C" void kernel_launch(void* const* d_in, const int* in_sizes, int n_in,
                              void* d_out, int out_size) {
    // Inputs: [0]=s_prev, [1]=hidden_states, [2]=Ww, [3]=Wb, [4]=Uw, [5]=Ub,
    //         [6]=Vw, [7]=Vb. Only hidden_states is live.
    const float4* hs = (const float4*)d_in[1];
    float* out = (float*)d_out;

    dim3 grid(BB, NCHUNK);
    fused_kernel<<<grid, NT>>>(hs, out);
}